// round 9
// baseline (speedup 1.0000x reference)
#include <cuda_runtime.h>
#include <cuda_fp16.h>
#include <cstdint>

#define N_NODES 100000
#define HF 64
#define E_MAX 1600000
#define NBLK_SCAN 391            // ceil(N_NODES/256)

// ---- fp8 e4m3 pack/unpack (sm_89+) -------------------------------------------
__device__ __forceinline__ unsigned short enc8(float hi, float lo) {
    unsigned short r;   // bits[15:8] = e4m3(hi), bits[7:0] = e4m3(lo)
    asm("cvt.rn.satfinite.e4m3x2.f32 %0, %1, %2;" : "=h"(r) : "f"(hi), "f"(lo));
    return r;
}
__device__ __forceinline__ float4 dec8x4(unsigned u) {
    unsigned short lo = (unsigned short)u;
    unsigned short hi = (unsigned short)(u >> 16);
    unsigned h0, h1;
    asm("cvt.rn.f16x2.e4m3x2 %0, %1;" : "=r"(h0) : "h"(lo));
    asm("cvt.rn.f16x2.e4m3x2 %0, %1;" : "=r"(h1) : "h"(hi));
    float2 f0 = __half22float2(*(__half2*)&h0);
    float2 f1 = __half22float2(*(__half2*)&h1);
    return make_float4(f0.x, f0.y, f1.x, f1.y);
}

// ---------------- scratch (static device globals; no allocation) -------------
__device__ __align__(16) unsigned char g_hs8[N_NODES * HF]; // dinv-scaled feats, e4m3
__device__ __align__(16) __half g_x[N_NODES * HF];          // layer activations, fp16
__device__ float g_dinv[N_NODES];
__device__ int   g_cnt[N_NODES];
__device__ int   g_off[N_NODES];
__device__ int   g_cur[N_NODES];
__device__ int   g_bsum[512];
__device__ int   g_csr[E_MAX];
__device__ int   g_is_i32 = 0;

// ---------------- prep -------------------------------------------------------
__global__ void k_init(const int* __restrict__ ei32, int nwords) {
    int i = blockIdx.x * 256 + threadIdx.x;
    if (i < N_NODES) { g_cnt[i] = 0; g_cur[i] = 0; }
    int w = 2 * i + 1;   // odd words: int64 high-halves are 0, int32 data isn't
    if (i < 2048 && w < nwords) {
        if (ei32[w] != 0) atomicOr(&g_is_i32, 1);
    }
}

__global__ void k_prep(const void* __restrict__ eiv, int E) {
    const bool i32 = (g_is_i32 != 0);
    const int* __restrict__ p32 = (const int*)eiv;
    const long long* __restrict__ p64 = (const long long*)eiv;
    int stride = gridDim.x * blockDim.x;
    for (int i = blockIdx.x * blockDim.x + threadIdx.x; i < E; i += stride) {
        int d = i32 ? p32[E + i] : (int)p64[(size_t)E + i];
        if ((unsigned)d >= N_NODES) d = 0;
        atomicAdd(&g_cnt[d], 1);
    }
}

__global__ __launch_bounds__(256) void k_scan1() {
    __shared__ int sh[256];
    int i = blockIdx.x * 256 + threadIdx.x;
    int c = (i < N_NODES) ? g_cnt[i] : 0;
    sh[threadIdx.x] = c;
    __syncthreads();
    int v = c;
#pragma unroll
    for (int ofs = 1; ofs < 256; ofs <<= 1) {
        int t = (threadIdx.x >= ofs) ? sh[threadIdx.x - ofs] : 0;
        __syncthreads();
        v += t;
        sh[threadIdx.x] = v;
        __syncthreads();
    }
    if (i < N_NODES) {
        g_off[i] = v - c;
        g_dinv[i] = rsqrtf((float)c + 1.0f);
    }
    if (threadIdx.x == 255) g_bsum[blockIdx.x] = v;
}

__global__ __launch_bounds__(512) void k_scan2() {
    __shared__ int sh[512];
    int t = threadIdx.x;
    int c = (t < NBLK_SCAN) ? g_bsum[t] : 0;
    sh[t] = c;
    __syncthreads();
    int v = c;
#pragma unroll
    for (int ofs = 1; ofs < 512; ofs <<= 1) {
        int x = (t >= ofs) ? sh[t - ofs] : 0;
        __syncthreads();
        v += x;
        sh[t] = v;
        __syncthreads();
    }
    if (t < NBLK_SCAN) g_bsum[t] = v - c;
}

__global__ __launch_bounds__(256) void k_fill(const void* __restrict__ eiv, int E) {
    const bool i32 = (g_is_i32 != 0);
    const int* __restrict__ p32 = (const int*)eiv;
    const long long* __restrict__ p64 = (const long long*)eiv;
    int stride = gridDim.x * blockDim.x;
    for (int e = blockIdx.x * blockDim.x + threadIdx.x; e < E; e += stride) {
        int s, d;
        if (i32) { s = p32[e]; d = p32[E + e]; }
        else     { s = (int)p64[e]; d = (int)p64[(size_t)E + e]; }
        if ((unsigned)s >= N_NODES) s = 0;
        if ((unsigned)d >= N_NODES) d = 0;
        int pos = g_off[d] + g_bsum[d >> 8] + atomicAdd(&g_cur[d], 1);
        g_csr[pos] = s;
    }
}

// ---------------- tensor-core GEMM ------------------------------------------
// C[M,64] = X[M,K] @ W[K,64] via mma.sync m16n8k16 (fp16 in, fp32 accum)
// HEAD=0: g_hs8[m][f] = e4m3(dinv[m] * C)
// HEAD=1: out[f*N+m]  = sigmoid(C + bias[f])  (transposed via smem staging)
#define MMA16816(d0,d1,d2,d3,a0,a1,a2,a3,b0,b1)                          \
    asm volatile("mma.sync.aligned.m16n8k16.row.col.f32.f16.f16.f32 "   \
                 "{%0,%1,%2,%3},{%4,%5,%6,%7},{%8,%9},{%0,%1,%2,%3};"   \
                 : "+f"(d0), "+f"(d1), "+f"(d2), "+f"(d3)               \
                 : "r"(a0), "r"(a1), "r"(a2), "r"(a3), "r"(b0), "r"(b1))

template <int K, bool XHALF, bool HEAD>
__global__ __launch_bounds__(256)
void k_mma(const float* __restrict__ Xf, const float* __restrict__ W,
           const float* __restrict__ bias, float* __restrict__ out)
{
    constexpr int BM = 128, BK = 64;
    constexpr int XSTR = 72;     // halves; conflict-free fragment loads
    constexpr int WSTR = 136;
    __shared__ __align__(16) char sraw[BM * XSTR * 2 + 64 * WSTR * 2];
    __half* Xs = (__half*)sraw;                       // [128][72]
    __half* Wt = (__half*)(sraw + BM * XSTR * 2);     // [64][136], Wt[n][k]=W[k][n]
    float*  stg = (float*)sraw;                       // head staging [128][68]

    const int tid  = threadIdx.x;
    const int w    = tid >> 5;
    const int lane = tid & 31;
    const int m0   = blockIdx.x * BM;
    const int r    = lane >> 2;
    const int q    = lane & 3;

    for (int idx = tid; idx < K * 64; idx += 256) {
        int k = idx >> 6, n = idx & 63;
        Wt[n * WSTR + k] = __float2half(W[idx]);
    }

    float acc[8][4];
#pragma unroll
    for (int j = 0; j < 8; j++) {
        acc[j][0] = acc[j][1] = acc[j][2] = acc[j][3] = 0.f;
    }

    for (int k0 = 0; k0 < K; k0 += BK) {
        if (XHALF) {
            for (int idx = tid; idx < BM * 8; idx += 256) {
                int m = idx >> 3, c = idx & 7;
                int gm = m0 + m;
                uint4 v = make_uint4(0, 0, 0, 0);
                if (gm < N_NODES)
                    v = *(const uint4*)((const __half*)g_x + (size_t)gm * 64 + 8 * c);
                *(uint4*)(Xs + m * XSTR + 8 * c) = v;
            }
        } else {
            for (int idx = tid; idx < BM * 32; idx += 256) {
                int m = idx >> 5, c = idx & 31;
                int gm = m0 + m;
                __half2 h = __floats2half2_rn(0.f, 0.f);
                if (gm < N_NODES) {
                    float2 v = *(const float2*)(Xf + (size_t)gm * K + k0 + 2 * c);
                    h = __floats2half2_rn(v.x, v.y);
                }
                *(__half2*)(Xs + m * XSTR + 2 * c) = h;
            }
        }
        __syncthreads();
#pragma unroll
        for (int kc = 0; kc < BK; kc += 16) {
            unsigned a0, a1, a2, a3;
            const __half* Ab = Xs + (16 * w + r) * XSTR + kc + 2 * q;
            a0 = *(const unsigned*)(Ab);
            a1 = *(const unsigned*)(Ab + 8 * XSTR);
            a2 = *(const unsigned*)(Ab + 8);
            a3 = *(const unsigned*)(Ab + 8 * XSTR + 8);
#pragma unroll
            for (int j = 0; j < 8; j++) {
                const __half* Bb = Wt + (8 * j + r) * WSTR + (k0 + kc) + 2 * q;
                unsigned b0 = *(const unsigned*)(Bb);
                unsigned b1 = *(const unsigned*)(Bb + 8);
                MMA16816(acc[j][0], acc[j][1], acc[j][2], acc[j][3],
                         a0, a1, a2, a3, b0, b1);
            }
        }
        __syncthreads();
    }

    if (!HEAD) {
        int row0 = m0 + 16 * w + r;
        int row1 = row0 + 8;
        if (row0 < N_NODES) {
            float dv = g_dinv[row0];
#pragma unroll
            for (int j = 0; j < 8; j++)
                *(unsigned short*)(g_hs8 + (size_t)row0 * 64 + 8 * j + 2 * q) =
                    enc8(dv * acc[j][1], dv * acc[j][0]);
        }
        if (row1 < N_NODES) {
            float dv = g_dinv[row1];
#pragma unroll
            for (int j = 0; j < 8; j++)
                *(unsigned short*)(g_hs8 + (size_t)row1 * 64 + 8 * j + 2 * q) =
                    enc8(dv * acc[j][3], dv * acc[j][2]);
        }
    } else {
        constexpr int SS = 68;
        int rl0 = 16 * w + r;
        int rl1 = rl0 + 8;
#pragma unroll
        for (int j = 0; j < 8; j++) {
            int col = 8 * j + 2 * q;
            float bx = bias[col], by = bias[col + 1];
            stg[rl0 * SS + col]     = 1.f / (1.f + __expf(-(acc[j][0] + bx)));
            stg[rl0 * SS + col + 1] = 1.f / (1.f + __expf(-(acc[j][1] + by)));
            stg[rl1 * SS + col]     = 1.f / (1.f + __expf(-(acc[j][2] + bx)));
            stg[rl1 * SS + col + 1] = 1.f / (1.f + __expf(-(acc[j][3] + by)));
        }
        __syncthreads();
        for (int idx = tid; idx < BM * 64; idx += 256) {
            int f = idx >> 7;
            int ml = idx & 127;
            int m = m0 + ml;
            if (m < N_NODES)
                out[(size_t)f * N_NODES + m] = stg[ml * SS + f];
        }
    }
}

// ---------------- gather + finalize: g_x = relu(dinv*(Σ hs[nbr] + hs_i) + b) --
// 16 lanes per node; lane owns 4 features = one uint32 of e4m3 per row.
__global__ __launch_bounds__(256)
void k_gather(const float* __restrict__ bias)
{
    int g = (blockIdx.x * 256 + threadIdx.x) >> 4;
    int l = threadIdx.x & 15;
    if (g >= N_NODES) return;

    const int beg = g_off[g] + g_bsum[g >> 8];
    const int deg = g_cnt[g];
    const int end = beg + deg;

    float4 acc = dec8x4(*(const unsigned*)(g_hs8 + (size_t)g * HF + 4 * l));

    int j = beg;
    for (; j + 4 <= end; j += 4) {
        int s0 = g_csr[j];
        int s1 = g_csr[j + 1];
        int s2 = g_csr[j + 2];
        int s3 = g_csr[j + 3];
        unsigned u0 = *(const unsigned*)(g_hs8 + (size_t)s0 * HF + 4 * l);
        unsigned u1 = *(const unsigned*)(g_hs8 + (size_t)s1 * HF + 4 * l);
        unsigned u2 = *(const unsigned*)(g_hs8 + (size_t)s2 * HF + 4 * l);
        unsigned u3 = *(const unsigned*)(g_hs8 + (size_t)s3 * HF + 4 * l);
        float4 f0 = dec8x4(u0);
        float4 f1 = dec8x4(u1);
        float4 f2 = dec8x4(u2);
        float4 f3 = dec8x4(u3);
        acc.x += (f0.x + f1.x) + (f2.x + f3.x);
        acc.y += (f0.y + f1.y) + (f2.y + f3.y);
        acc.z += (f0.z + f1.z) + (f2.z + f3.z);
        acc.w += (f0.w + f1.w) + (f2.w + f3.w);
    }
    for (; j < end; j++) {
        int s0 = g_csr[j];
        float4 f0 = dec8x4(*(const unsigned*)(g_hs8 + (size_t)s0 * HF + 4 * l));
        acc.x += f0.x; acc.y += f0.y; acc.z += f0.z; acc.w += f0.w;
    }

    float dv = g_dinv[g];
    float4 b = *(const float4*)(bias + 4 * l);
    float ox = fmaxf(fmaf(dv, acc.x, b.x), 0.f);
    float oy = fmaxf(fmaf(dv, acc.y, b.y), 0.f);
    float oz = fmaxf(fmaf(dv, acc.z, b.z), 0.f);
    float ow = fmaxf(fmaf(dv, acc.w, b.w), 0.f);
    __half2 h0 = __floats2half2_rn(ox, oy);
    __half2 h1 = __floats2half2_rn(oz, ow);
    uint2 u;
    u.x = *(unsigned*)&h0;
    u.y = *(unsigned*)&h1;
    *(uint2*)(g_x + (size_t)g * HF + 4 * l) = u;
}

// ---------------- launch ------------------------------------------------------
extern "C" void kernel_launch(void* const* d_in, const int* in_sizes, int n_in,
                              void* d_out, int out_size)
{
    const float* x  = (const float*)d_in[0];
    const void*  ei = d_in[1];
    const float* W1 = (const float*)d_in[2];
    const float* b1 = (const float*)d_in[3];
    const float* W2 = (const float*)d_in[4];
    const float* b2 = (const float*)d_in[5];
    const float* Wl = (const float*)d_in[6];
    const float* bl = (const float*)d_in[7];
    float*       out = (float*)d_out;
    const int nwords = in_sizes[1];
    const int E = nwords / 2;

    const int nblk = NBLK_SCAN;                           // 391
    const int gemm_blocks = (N_NODES + 127) / 128;        // 782
    const int gather_blocks = (N_NODES * 16 + 255) / 256; // 6250

    // ---- graph prep ----
    k_init<<<nblk, 256>>>((const int*)ei, nwords);
    k_prep<<<2048, 256>>>(ei, E);
    k_scan1<<<nblk, 256>>>();
    k_scan2<<<1, 512>>>();
    k_fill<<<2048, 256>>>(ei, E);

    // ---- layer 1 ----
    k_mma<128, false, false><<<gemm_blocks, 256>>>(x, W1, nullptr, nullptr);
    k_gather<<<gather_blocks, 256>>>(b1);

    // ---- layer 2 ----
    k_mma<64, true, false><<<gemm_blocks, 256>>>(nullptr, W2, nullptr, nullptr);
    k_gather<<<gather_blocks, 256>>>(b2);

    // ---- head: sigmoid(g_x @ Wl + bl), transposed store ----
    k_mma<64, true, true><<<gemm_blocks, 256>>>(nullptr, Wl, bl, out);

    (void)n_in; (void)out_size;
}